// round 2
// baseline (speedup 1.0000x reference)
#include <cuda_runtime.h>
#include <math.h>

#define BB 2
#define LL 2048
#define DD 512
#define NHA 32
#define HDA 16
#define DIN 1024
#define NHM 16
#define PP 64
#define NNc 64
#define CONVD 1152
#define DPROJ 2192
#define EPSF 1e-5f
#define ROWS (BB*LL)

// ---------------- scratch (static device buffers; no allocation) ----------------
__device__ float g_qkv[ROWS * 3 * DD];
__device__ float g_attno[ROWS * DD];
__device__ float g_aproj[ROWS * DD];
__device__ float g_h1[ROWS * DD];
__device__ float g_zx0[ROWS * DPROJ];
__device__ float g_zx1[ROWS * DPROJ];
__device__ float g_xbc0[ROWS * CONVD];
__device__ float g_xbc1[ROWS * CONVD];
__device__ float g_dt0[ROWS * NHM];
__device__ float g_dt1[ROWS * NHM];
__device__ float g_dA0[ROWS * NHM];
__device__ float g_dA1[ROWS * NHM];
__device__ float g_y0[ROWS * DIN];
__device__ float g_y1[ROWS * DIN];
__device__ float g_acc[ROWS * DD];

// ---------------- generic NT GEMM: C = A[M,K] @ W[N,K]^T (+bias) (+addsrc) ------
// revA: read A rows sequence-reversed (per batch of 2048)
// revC: write C rows sequence-reversed; accum: C += instead of C =
__global__ void gemm_nt(const float* __restrict__ A, const float* __restrict__ W,
                        const float* __restrict__ bias, const float* __restrict__ addsrc,
                        float* __restrict__ C, int Nn, int Kk,
                        int revA, int revC, int accum)
{
    __shared__ float As[16][128];
    __shared__ float Bs[16][64];
    int t = threadIdx.x;
    int m0 = blockIdx.y * 128;
    int n0 = blockIdx.x * 64;
    int tx = t & 15, ty = t >> 4;
    float acc[8][4];
#pragma unroll
    for (int i = 0; i < 8; i++)
#pragma unroll
        for (int j = 0; j < 4; j++) acc[i][j] = 0.f;

    for (int k0 = 0; k0 < Kk; k0 += 16) {
#pragma unroll
        for (int i = 0; i < 2; i++) {
            int idx = t + i * 256;        // 0..511
            int row = idx >> 2;           // 0..127
            int c4  = (idx & 3) << 2;
            int m = m0 + row;
            int mr = revA ? ((m & ~2047) + (2047 - (m & 2047))) : m;
            float4 v = *(const float4*)(A + (size_t)mr * Kk + k0 + c4);
            As[c4 + 0][row] = v.x; As[c4 + 1][row] = v.y;
            As[c4 + 2][row] = v.z; As[c4 + 3][row] = v.w;
        }
        {
            int row = t >> 2;             // 0..63
            int c4  = (t & 3) << 2;
            int n = n0 + row;
            float4 v = make_float4(0.f, 0.f, 0.f, 0.f);
            if (n < Nn) v = *(const float4*)(W + (size_t)n * Kk + k0 + c4);
            Bs[c4 + 0][row] = v.x; Bs[c4 + 1][row] = v.y;
            Bs[c4 + 2][row] = v.z; Bs[c4 + 3][row] = v.w;
        }
        __syncthreads();
#pragma unroll
        for (int k = 0; k < 16; k++) {
            float a0[8], b0[4];
#pragma unroll
            for (int i = 0; i < 8; i++) a0[i] = As[k][ty * 8 + i];
#pragma unroll
            for (int j = 0; j < 4; j++) b0[j] = Bs[k][tx * 4 + j];
#pragma unroll
            for (int i = 0; i < 8; i++)
#pragma unroll
                for (int j = 0; j < 4; j++)
                    acc[i][j] = fmaf(a0[i], b0[j], acc[i][j]);
        }
        __syncthreads();
    }
#pragma unroll
    for (int i = 0; i < 8; i++) {
        int m = m0 + ty * 8 + i;
        int mo = revC ? ((m & ~2047) + (2047 - (m & 2047))) : m;
#pragma unroll
        for (int j = 0; j < 4; j++) {
            int n = n0 + tx * 4 + j;
            if (n >= Nn) continue;
            float v = acc[i][j];
            if (bias)   v += bias[n];
            if (addsrc) v += addsrc[(size_t)m * Nn + n];
            float* cp = C + (size_t)mo * Nn + n;
            if (accum) *cp += v; else *cp = v;
        }
    }
}

// ---------------- attention: flash-style, 64 queries/block, 1 thread = 1 row ----
__global__ void attn_kernel(const float* __restrict__ qkv, float* __restrict__ out)
{
    int b = blockIdx.z, h = blockIdx.y;
    int tid = threadIdx.x;                 // 64 threads
    int i = blockIdx.x * 64 + tid;
    __shared__ float Ks[64][16];
    __shared__ float Vs[64][16];
    float q[16];
    const float* qrow = qkv + ((size_t)(b * LL + i)) * 1536 + h * 16;
#pragma unroll
    for (int d = 0; d < 16; d++) q[d] = qrow[d] * 0.25f;  // 1/sqrt(16)
    float o[16];
#pragma unroll
    for (int d = 0; d < 16; d++) o[d] = 0.f;
    float mi = -3.0e38f, li = 0.f;

    for (int j0 = 0; j0 < LL; j0 += 64) {
        __syncthreads();
        {
            const float* kr = qkv + ((size_t)(b * LL + j0 + tid)) * 1536 + 512 + h * 16;
#pragma unroll
            for (int d = 0; d < 16; d += 4) {
                float4 kv = *(const float4*)(kr + d);
                Ks[tid][d] = kv.x; Ks[tid][d + 1] = kv.y; Ks[tid][d + 2] = kv.z; Ks[tid][d + 3] = kv.w;
                float4 vv = *(const float4*)(kr + 512 + d);
                Vs[tid][d] = vv.x; Vs[tid][d + 1] = vv.y; Vs[tid][d + 2] = vv.z; Vs[tid][d + 3] = vv.w;
            }
        }
        __syncthreads();
        float sv[64];
#pragma unroll
        for (int j = 0; j < 64; j++) {
            float s = 0.f;
#pragma unroll
            for (int d = 0; d < 16; d++) s = fmaf(q[d], Ks[j][d], s);
            sv[j] = s;
        }
        float mt = mi;
#pragma unroll
        for (int j = 0; j < 64; j++) mt = fmaxf(mt, sv[j]);
        float alpha = __expf(mi - mt);
        li *= alpha;
#pragma unroll
        for (int d = 0; d < 16; d++) o[d] *= alpha;
#pragma unroll
        for (int j = 0; j < 64; j++) {
            float p = __expf(sv[j] - mt);
            li += p;
#pragma unroll
            for (int d = 0; d < 16; d++) o[d] = fmaf(p, Vs[j][d], o[d]);
        }
        mi = mt;
    }
    float inv = 1.f / li;
    float* orow = out + ((size_t)(b * LL + i)) * DD + h * 16;
#pragma unroll
    for (int d = 0; d < 16; d++) orow[d] = o[d] * inv;
}

// ---------------- layernorm over 512 (warp per row), optional residual add -----
__global__ void ln_kernel(const float* __restrict__ X, const float* __restrict__ Yadd,
                          const float* __restrict__ g, const float* __restrict__ bb,
                          float* __restrict__ out)
{
    int warp = (blockIdx.x * blockDim.x + threadIdx.x) >> 5;
    int lane = threadIdx.x & 31;
    if (warp >= ROWS) return;
    const float* x = X + (size_t)warp * DD;
    float v[16];
    float sum = 0.f;
#pragma unroll
    for (int i = 0; i < 16; i++) {
        int c = lane + i * 32;
        float tv = x[c];
        if (Yadd) tv += Yadd[(size_t)warp * DD + c];
        v[i] = tv; sum += tv;
    }
#pragma unroll
    for (int o = 16; o > 0; o >>= 1) sum += __shfl_xor_sync(0xffffffffu, sum, o);
    float mean = sum * (1.f / DD);
    float vs = 0.f;
#pragma unroll
    for (int i = 0; i < 16; i++) { float d = v[i] - mean; vs = fmaf(d, d, vs); }
#pragma unroll
    for (int o = 16; o > 0; o >>= 1) vs += __shfl_xor_sync(0xffffffffu, vs, o);
    float r = rsqrtf(vs * (1.f / DD) + EPSF);
    float* op = out + (size_t)warp * DD;
#pragma unroll
    for (int i = 0; i < 16; i++) {
        int c = lane + i * 32;
        op[c] = (v[i] - mean) * r * g[c] + bb[c];
    }
}

// ---------------- depthwise causal conv (K=4) + silu ---------------------------
__global__ void conv_kernel(const float* __restrict__ zx, const float* __restrict__ cw,
                            const float* __restrict__ cb, float* __restrict__ xbc)
{
    int idx = blockIdx.x * blockDim.x + threadIdx.x;
    if (idx >= ROWS * CONVD) return;
    int c = idx % CONVD;
    int bl = idx / CONVD;
    int l = bl & 2047;
    const float* base = zx + (size_t)bl * DPROJ + DIN + c;
    float4 w = *(const float4*)(cw + c * 4);
    float a = cb[c];
    if (l >= 3) a = fmaf(base[-3 * DPROJ], w.x, a);
    if (l >= 2) a = fmaf(base[-2 * DPROJ], w.y, a);
    if (l >= 1) a = fmaf(base[-1 * DPROJ], w.z, a);
    a = fmaf(base[0], w.w, a);
    xbc[idx] = a * (1.f / (1.f + __expf(-a)));
}

// ---------------- dt = softplus(raw + bias), dA = exp(dt * -exp(A_log)) --------
__global__ void dtdA_kernel(const float* __restrict__ zx, const float* __restrict__ dtb,
                            const float* __restrict__ Alog,
                            float* __restrict__ dt, float* __restrict__ dA)
{
    int idx = blockIdx.x * blockDim.x + threadIdx.x;
    if (idx >= ROWS * NHM) return;
    int hm = idx & 15;
    int bl = idx >> 4;
    float raw = zx[(size_t)bl * DPROJ + (DPROJ - NHM) + hm] + dtb[hm];
    float dtv = (raw > 20.f) ? raw : log1pf(__expf(raw));
    float dAv = __expf(-__expf(Alog[hm]) * dtv);
    dt[idx] = dtv; dA[idx] = dAv;
}

// ---------------- sequential SSM scan, both directions in one launch ------------
// grid (4 p-chunks, 16 heads, 4 = {b0,b1}x{fwd,bwd}); 256 threads
// thread t: p_local = t>>4 (16 rows), nsub = t&15 -> 4 n-values each (64 n total)
__global__ void scan_kernel(
    const float* __restrict__ xbc0, const float* __restrict__ dt0, const float* __restrict__ dA0,
    const float* __restrict__ Dp0, float* __restrict__ y0,
    const float* __restrict__ xbc1, const float* __restrict__ dt1, const float* __restrict__ dA1,
    const float* __restrict__ Dp1, float* __restrict__ y1)
{
    int z = blockIdx.z;
    int b = z & 1, dir = z >> 1;
    const float* xbc = dir ? xbc1 : xbc0;
    const float* dtp = dir ? dt1 : dt0;
    const float* dAp = dir ? dA1 : dA0;
    const float* Dp  = dir ? Dp1 : Dp0;
    float* y         = dir ? y1 : y0;
    int h = blockIdx.y, pc = blockIdx.x;
    int t = threadIdx.x;
    int p_local = t >> 4, nsub = t & 15, n0c = nsub << 2;

    __shared__ float sm[2][160]; // [buf][ x:0..15 | B:16..79 | C:80..143 | dt:144 | dA:145 ]

    int kind = 3, roff = 0;      // 0: xbc col, 1: dt, 2: dA, 3: inactive
    if (t < 16)       { kind = 0; roff = h * 64 + pc * 16 + t; }
    else if (t < 80)  { kind = 0; roff = DIN + (t - 16); }
    else if (t < 144) { kind = 0; roff = DIN + NNc + (t - 80); }
    else if (t == 144) kind = 1;
    else if (t == 145) kind = 2;

    size_t base_bl = (size_t)b * LL;
    float s0 = 0.f, s1 = 0.f, s2 = 0.f, s3 = 0.f;
    float dcoef = Dp[h];

    float rv = 0.f;
    if (kind == 0)      rv = xbc[base_bl * CONVD + roff];
    else if (kind == 1) rv = dtp[base_bl * NHM + h];
    else if (kind == 2) rv = dAp[base_bl * NHM + h];

    int buf = 0;
    for (int l = 0; l < LL; l++) {
        if (t < 146) sm[buf][t] = rv;
        __syncthreads();
        if (l + 1 < LL) {  // prefetch next step while computing this one
            if (kind == 0)      rv = xbc[(base_bl + l + 1) * CONVD + roff];
            else if (kind == 1) rv = dtp[(base_bl + l + 1) * NHM + h];
            else if (kind == 2) rv = dAp[(base_bl + l + 1) * NHM + h];
        }
        float dtv = sm[buf][144];
        float dAv = sm[buf][145];
        float xv  = sm[buf][p_local];
        float cx  = dtv * xv;
        float4 Bv = *(const float4*)&sm[buf][16 + n0c];
        float4 Cv = *(const float4*)&sm[buf][80 + n0c];
        s0 = fmaf(s0, dAv, cx * Bv.x);
        s1 = fmaf(s1, dAv, cx * Bv.y);
        s2 = fmaf(s2, dAv, cx * Bv.z);
        s3 = fmaf(s3, dAv, cx * Bv.w);
        float part = s0 * Cv.x + s1 * Cv.y + s2 * Cv.z + s3 * Cv.w;
        part += __shfl_xor_sync(0xffffffffu, part, 1);
        part += __shfl_xor_sync(0xffffffffu, part, 2);
        part += __shfl_xor_sync(0xffffffffu, part, 4);
        part += __shfl_xor_sync(0xffffffffu, part, 8);
        if (nsub == 0)
            y[(base_bl + l) * DIN + h * 64 + pc * 16 + p_local] = part + dcoef * xv;
        buf ^= 1;
    }
}

// ---------------- gated RMSNorm (in-place on y), warp per 1024-row --------------
__global__ void rmsgate_kernel(float* __restrict__ y, const float* __restrict__ zx,
                               const float* __restrict__ nw)
{
    int warp = (blockIdx.x * blockDim.x + threadIdx.x) >> 5;
    int lane = threadIdx.x & 31;
    if (warp >= ROWS) return;
    const float* zr = zx + (size_t)warp * DPROJ;
    float* yr = y + (size_t)warp * DIN;
    float v[32];
    float ss = 0.f;
#pragma unroll
    for (int i = 0; i < 32; i++) {
        int c = lane + i * 32;
        float zv = zr[c];
        float yv = yr[c] * (zv * (1.f / (1.f + __expf(-zv))));  // y * silu(z)
        v[i] = yv; ss = fmaf(yv, yv, ss);
    }
#pragma unroll
    for (int o = 16; o > 0; o >>= 1) ss += __shfl_xor_sync(0xffffffffu, ss, o);
    float r = rsqrtf(ss * (1.f / DIN) + EPSF);
#pragma unroll
    for (int i = 0; i < 32; i++) {
        int c = lane + i * 32;
        yr[c] = v[i] * r * nw[c];
    }
}

// ---------------- launcher -----------------------------------------------------
extern "C" void kernel_launch(void* const* d_in, const int* in_sizes, int n_in,
                              void* d_out, int out_size)
{
    const float* h      = (const float*)d_in[0];
    const float* Wqkv   = (const float*)d_in[1];
    const float* bqkv   = (const float*)d_in[2];
    const float* Wo_a   = (const float*)d_in[3];
    const float* bo_a   = (const float*)d_in[4];
    const float* g1     = (const float*)d_in[5];
    const float* b1     = (const float*)d_in[6];
    const float* g2     = (const float*)d_in[7];
    const float* b2     = (const float*)d_in[8];
    const float* f_Wi   = (const float*)d_in[9];
    const float* f_cw   = (const float*)d_in[10];
    const float* f_cb   = (const float*)d_in[11];
    const float* f_dtb  = (const float*)d_in[12];
    const float* f_Alog = (const float*)d_in[13];
    const float* f_D    = (const float*)d_in[14];
    const float* f_nw   = (const float*)d_in[15];
    const float* f_Wo   = (const float*)d_in[16];
    const float* bw_Wi  = (const float*)d_in[17];
    const float* bw_cw  = (const float*)d_in[18];
    const float* bw_cb  = (const float*)d_in[19];
    const float* bw_dtb = (const float*)d_in[20];
    const float* bw_Alog= (const float*)d_in[21];
    const float* bw_D   = (const float*)d_in[22];
    const float* bw_nw  = (const float*)d_in[23];
    const float* bw_Wo  = (const float*)d_in[24];
    float* out = (float*)d_out;

    float *qkvb, *attno, *aproj, *h1, *zx0, *zx1, *xbc0, *xbc1;
    float *dt0, *dt1, *dA0, *dA1, *y0, *y1, *acc;
    cudaGetSymbolAddress((void**)&qkvb, g_qkv);
    cudaGetSymbolAddress((void**)&attno, g_attno);
    cudaGetSymbolAddress((void**)&aproj, g_aproj);
    cudaGetSymbolAddress((void**)&h1, g_h1);
    cudaGetSymbolAddress((void**)&zx0, g_zx0);
    cudaGetSymbolAddress((void**)&zx1, g_zx1);
    cudaGetSymbolAddress((void**)&xbc0, g_xbc0);
    cudaGetSymbolAddress((void**)&xbc1, g_xbc1);
    cudaGetSymbolAddress((void**)&dt0, g_dt0);
    cudaGetSymbolAddress((void**)&dt1, g_dt1);
    cudaGetSymbolAddress((void**)&dA0, g_dA0);
    cudaGetSymbolAddress((void**)&dA1, g_dA1);
    cudaGetSymbolAddress((void**)&y0, g_y0);
    cudaGetSymbolAddress((void**)&y1, g_y1);
    cudaGetSymbolAddress((void**)&acc, g_acc);

    // 1) qkv = h @ Wqkv^T + bqkv
    gemm_nt<<<dim3(24, 32), 256>>>(h, Wqkv, bqkv, nullptr, qkvb, 1536, 512, 0, 0, 0);
    // 2) attention
    attn_kernel<<<dim3(32, 32, 2), 64>>>(qkvb, attno);
    // 3) attn out-proj
    gemm_nt<<<dim3(8, 32), 256>>>(attno, Wo_a, bo_a, nullptr, aproj, 512, 512, 0, 0, 0);
    // 4) h1 = LN(h + aproj)
    ln_kernel<<<512, 256>>>(h, aproj, g1, b1, h1);
    // 5) mamba in-projections (fwd; bwd reads h1 reversed)
    gemm_nt<<<dim3(35, 32), 256>>>(h1, f_Wi, nullptr, nullptr, zx0, DPROJ, 512, 0, 0, 0);
    gemm_nt<<<dim3(35, 32), 256>>>(h1, bw_Wi, nullptr, nullptr, zx1, DPROJ, 512, 1, 0, 0);
    // 6) depthwise conv + silu
    conv_kernel<<<(ROWS * CONVD + 255) / 256, 256>>>(zx0, f_cw, f_cb, xbc0);
    conv_kernel<<<(ROWS * CONVD + 255) / 256, 256>>>(zx1, bw_cw, bw_cb, xbc1);
    // 7) dt / dA
    dtdA_kernel<<<256, 256>>>(zx0, f_dtb, f_Alog, dt0, dA0);
    dtdA_kernel<<<256, 256>>>(zx1, bw_dtb, bw_Alog, dt1, dA1);
    // 8) SSM scan, both directions concurrently
    scan_kernel<<<dim3(4, 16, 4), 256>>>(xbc0, dt0, dA0, f_D, y0,
                                         xbc1, dt1, dA1, bw_D, y1);
    // 9) gated RMSNorm (in place)
    rmsgate_kernel<<<512, 256>>>(y0, zx0, f_nw);
    rmsgate_kernel<<<512, 256>>>(y1, zx1, bw_nw);
    // 10) out-projections: acc = h1 + yf@Wo^T ; acc[rev] += yb@Wo^T
    gemm_nt<<<dim3(8, 32), 256>>>(y0, f_Wo, nullptr, h1, acc, 512, 1024, 0, 0, 0);
    gemm_nt<<<dim3(8, 32), 256>>>(y1, bw_Wo, nullptr, nullptr, acc, 512, 1024, 0, 1, 1);
    // 11) final LN
    ln_kernel<<<512, 256>>>(acc, nullptr, g2, b2, out);
}

// round 5
// speedup vs baseline: 1.0733x; 1.0733x over previous
#include <cuda_runtime.h>
#include <math.h>
#include <stdint.h>

#define BB 2
#define LL 2048
#define DD 512
#define NHA 32
#define HDA 16
#define DIN 1024
#define NHM 16
#define PP 64
#define NNc 64
#define CONVD 1152
#define DPROJ 2192
#define EPSF 1e-5f
#define ROWS (BB*LL)

// ---------------- scratch (static device buffers; no allocation) ----------------
__device__ float g_qkv[ROWS * 3 * DD];
__device__ float g_attno[ROWS * DD];
__device__ float g_aproj[ROWS * DD];
__device__ float g_h1[ROWS * DD];
__device__ float g_zx0[ROWS * DPROJ];
__device__ float g_zx1[ROWS * DPROJ];
__device__ float g_xbc0[ROWS * CONVD];
__device__ float g_xbc1[ROWS * CONVD];
__device__ float g_dt0[ROWS * NHM];
__device__ float g_dt1[ROWS * NHM];
__device__ float g_dA0[ROWS * NHM];
__device__ float g_dA1[ROWS * NHM];
__device__ float g_y0[ROWS * DIN];
__device__ float g_y1[ROWS * DIN];
__device__ float g_acc[ROWS * DD];

// ---------------- tf32 helpers -------------------------------------------------
__device__ __forceinline__ uint32_t f2tf32(float x) {
    uint32_t r;
    asm("cvt.rna.tf32.f32 %0, %1;" : "=r"(r) : "f"(x));
    return r;
}

__device__ __forceinline__ void mma_tf32(float c[4],
                                         uint32_t a0, uint32_t a1, uint32_t a2, uint32_t a3,
                                         uint32_t b0, uint32_t b1)
{
    asm volatile(
        "mma.sync.aligned.m16n8k8.row.col.f32.tf32.tf32.f32 "
        "{%0,%1,%2,%3}, {%4,%5,%6,%7}, {%8,%9}, {%0,%1,%2,%3};"
        : "+f"(c[0]), "+f"(c[1]), "+f"(c[2]), "+f"(c[3])
        : "r"(a0), "r"(a1), "r"(a2), "r"(a3), "r"(b0), "r"(b1));
}

// ---------------- NT GEMM via 3xTF32 tensor-core mma ---------------------------
// C[M,Nn] = A[M,K] @ W[Nn,K]^T (+bias) (+addsrc), fp32-accurate via hi/lo split.
// Block tile 128x64, 8 warps (4 over M x 2 over N), warp tile 32x32.
#define LDA 132
#define LDB 68
__global__ __launch_bounds__(256) void gemm_nt(
    const float* __restrict__ A, const float* __restrict__ W,
    const float* __restrict__ bias, const float* __restrict__ addsrc,
    float* __restrict__ C, int Nn, int Kk,
    int revA, int revC, int accum)
{
    __shared__ float As[16 * LDA];
    __shared__ float Bs[16 * LDB];
    int t = threadIdx.x;
    int lane = t & 31, w = t >> 5;
    int wm = w & 3, wn = w >> 2;          // 4 warps over M, 2 over N
    int m0 = blockIdx.y * 128;
    int n0 = blockIdx.x * 64;
    int g = lane >> 2, tg = lane & 3;     // fragment row-group / in-group id

    float acc[2][4][4];
#pragma unroll
    for (int mi = 0; mi < 2; mi++)
#pragma unroll
        for (int ni = 0; ni < 4; ni++)
#pragma unroll
            for (int e = 0; e < 4; e++) acc[mi][ni][e] = 0.f;

    for (int k0 = 0; k0 < Kk; k0 += 16) {
        // stage A tile 128x16 (transposed to [k][m] in smem)
#pragma unroll
        for (int i = 0; i < 2; i++) {
            int idx = t + i * 256;            // 0..511
            int row = idx >> 2;               // m 0..127
            int c4  = (idx & 3) << 2;         // k 0,4,8,12
            int m = m0 + row;
            int mr = revA ? ((m & ~2047) + (2047 - (m & 2047))) : m;
            float4 v = *(const float4*)(A + (size_t)mr * Kk + k0 + c4);
            As[(c4 + 0) * LDA + row] = v.x;
            As[(c4 + 1) * LDA + row] = v.y;
            As[(c4 + 2) * LDA + row] = v.z;
            As[(c4 + 3) * LDA + row] = v.w;
        }
        // stage B tile 64x16 (transposed to [k][n])
        {
            int row = t >> 2;                 // n 0..63
            int c4  = (t & 3) << 2;
            int n = n0 + row;
            float4 v = make_float4(0.f, 0.f, 0.f, 0.f);
            if (n < Nn) v = *(const float4*)(W + (size_t)n * Kk + k0 + c4);
            Bs[(c4 + 0) * LDB + row] = v.x;
            Bs[(c4 + 1) * LDB + row] = v.y;
            Bs[(c4 + 2) * LDB + row] = v.z;
            Bs[(c4 + 3) * LDB + row] = v.w;
        }
        __syncthreads();

#pragma unroll
        for (int ks = 0; ks < 16; ks += 8) {
            uint32_t ahi[2][4], alo[2][4];
#pragma unroll
            for (int mi = 0; mi < 2; mi++) {
                int mb = wm * 32 + mi * 16;
                float a0 = As[(ks + tg) * LDA + mb + g];
                float a1 = As[(ks + tg) * LDA + mb + g + 8];
                float a2 = As[(ks + tg + 4) * LDA + mb + g];
                float a3 = As[(ks + tg + 4) * LDA + mb + g + 8];
                ahi[mi][0] = f2tf32(a0); alo[mi][0] = __float_as_uint(a0 - __uint_as_float(ahi[mi][0]));
                ahi[mi][1] = f2tf32(a1); alo[mi][1] = __float_as_uint(a1 - __uint_as_float(ahi[mi][1]));
                ahi[mi][2] = f2tf32(a2); alo[mi][2] = __float_as_uint(a2 - __uint_as_float(ahi[mi][2]));
                ahi[mi][3] = f2tf32(a3); alo[mi][3] = __float_as_uint(a3 - __uint_as_float(ahi[mi][3]));
            }
            uint32_t bhi[4][2], blo[4][2];
#pragma unroll
            for (int ni = 0; ni < 4; ni++) {
                int nb = wn * 32 + ni * 8;
                float b0 = Bs[(ks + tg) * LDB + nb + g];
                float b1 = Bs[(ks + tg + 4) * LDB + nb + g];
                bhi[ni][0] = f2tf32(b0); blo[ni][0] = __float_as_uint(b0 - __uint_as_float(bhi[ni][0]));
                bhi[ni][1] = f2tf32(b1); blo[ni][1] = __float_as_uint(b1 - __uint_as_float(bhi[ni][1]));
            }
#pragma unroll
            for (int mi = 0; mi < 2; mi++)
#pragma unroll
                for (int ni = 0; ni < 4; ni++) {
                    mma_tf32(acc[mi][ni], ahi[mi][0], ahi[mi][1], ahi[mi][2], ahi[mi][3],
                             bhi[ni][0], bhi[ni][1]);
                    mma_tf32(acc[mi][ni], ahi[mi][0], ahi[mi][1], ahi[mi][2], ahi[mi][3],
                             blo[ni][0], blo[ni][1]);
                    mma_tf32(acc[mi][ni], alo[mi][0], alo[mi][1], alo[mi][2], alo[mi][3],
                             bhi[ni][0], bhi[ni][1]);
                }
        }
        __syncthreads();
    }

    // epilogue
#pragma unroll
    for (int mi = 0; mi < 2; mi++) {
#pragma unroll
        for (int ni = 0; ni < 4; ni++) {
            int row0 = m0 + wm * 32 + mi * 16 + g;
            int col0 = n0 + wn * 32 + ni * 8 + 2 * tg;
#pragma unroll
            for (int rr = 0; rr < 2; rr++) {
                int m = row0 + rr * 8;
                int mo = revC ? ((m & ~2047) + (2047 - (m & 2047))) : m;
#pragma unroll
                for (int cc = 0; cc < 2; cc++) {
                    int n = col0 + cc;
                    if (n >= Nn) continue;
                    float v = acc[mi][ni][rr * 2 + cc];
                    if (bias)   v += bias[n];
                    if (addsrc) v += addsrc[(size_t)m * Nn + n];
                    float* cp = C + (size_t)mo * Nn + n;
                    if (accum) *cp += v; else *cp = v;
                }
            }
        }
    }
}

// ---------------- attention: flash-style, 64 queries/block, 1 thread = 1 row ----
__global__ void attn_kernel(const float* __restrict__ qkv, float* __restrict__ out)
{
    int b = blockIdx.z, h = blockIdx.y;
    int tid = threadIdx.x;                 // 64 threads
    int i = blockIdx.x * 64 + tid;
    __shared__ float Ks[64][16];
    __shared__ float Vs[64][16];
    float q[16];
    const float* qrow = qkv + ((size_t)(b * LL + i)) * 1536 + h * 16;
#pragma unroll
    for (int d = 0; d < 16; d++) q[d] = qrow[d] * 0.25f;  // 1/sqrt(16)
    float o[16];
#pragma unroll
    for (int d = 0; d < 16; d++) o[d] = 0.f;
    float mi = -3.0e38f, li = 0.f;

    for (int j0 = 0; j0 < LL; j0 += 64) {
        __syncthreads();
        {
            const float* kr = qkv + ((size_t)(b * LL + j0 + tid)) * 1536 + 512 + h * 16;
#pragma unroll
            for (int d = 0; d < 16; d += 4) {
                float4 kv = *(const float4*)(kr + d);
                Ks[tid][d] = kv.x; Ks[tid][d + 1] = kv.y; Ks[tid][d + 2] = kv.z; Ks[tid][d + 3] = kv.w;
                float4 vv = *(const float4*)(kr + 512 + d);
                Vs[tid][d] = vv.x; Vs[tid][d + 1] = vv.y; Vs[tid][d + 2] = vv.z; Vs[tid][d + 3] = vv.w;
            }
        }
        __syncthreads();
        float sv[64];
#pragma unroll
        for (int j = 0; j < 64; j++) {
            float s = 0.f;
#pragma unroll
            for (int d = 0; d < 16; d++) s = fmaf(q[d], Ks[j][d], s);
            sv[j] = s;
        }
        float mt = mi;
#pragma unroll
        for (int j = 0; j < 64; j++) mt = fmaxf(mt, sv[j]);
        float alpha = __expf(mi - mt);
        li *= alpha;
#pragma unroll
        for (int d = 0; d < 16; d++) o[d] *= alpha;
#pragma unroll
        for (int j = 0; j < 64; j++) {
            float p = __expf(sv[j] - mt);
            li += p;
#pragma unroll
            for (int d = 0; d < 16; d++) o[d] = fmaf(p, Vs[j][d], o[d]);
        }
        mi = mt;
    }
    float inv = 1.f / li;
    float* orow = out + ((size_t)(b * LL + i)) * DD + h * 16;
#pragma unroll
    for (int d = 0; d < 16; d++) orow[d] = o[d] * inv;
}

// ---------------- layernorm over 512 (warp per row), optional residual add -----
__global__ void ln_kernel(const float* __restrict__ X, const float* __restrict__ Yadd,
                          const float* __restrict__ g, const float* __restrict__ bb,
                          float* __restrict__ out)
{
    int warp = (blockIdx.x * blockDim.x + threadIdx.x) >> 5;
    int lane = threadIdx.x & 31;
    if (warp >= ROWS) return;
    const float* x = X + (size_t)warp * DD;
    float v[16];
    float sum = 0.f;
#pragma unroll
    for (int i = 0; i < 16; i++) {
        int c = lane + i * 32;
        float tv = x[c];
        if (Yadd) tv += Yadd[(size_t)warp * DD + c];
        v[i] = tv; sum += tv;
    }
#pragma unroll
    for (int o = 16; o > 0; o >>= 1) sum += __shfl_xor_sync(0xffffffffu, sum, o);
    float mean = sum * (1.f / DD);
    float vs = 0.f;
#pragma unroll
    for (int i = 0; i < 16; i++) { float d = v[i] - mean; vs = fmaf(d, d, vs); }
#pragma unroll
    for (int o = 16; o > 0; o >>= 1) vs += __shfl_xor_sync(0xffffffffu, vs, o);
    float r = rsqrtf(vs * (1.f / DD) + EPSF);
    float* op = out + (size_t)warp * DD;
#pragma unroll
    for (int i = 0; i < 16; i++) {
        int c = lane + i * 32;
        op[c] = (v[i] - mean) * r * g[c] + bb[c];
    }
}

// ---------------- depthwise causal conv (K=4) + silu ---------------------------
__global__ void conv_kernel(const float* __restrict__ zx, const float* __restrict__ cw,
                            const float* __restrict__ cb, float* __restrict__ xbc)
{
    int idx = blockIdx.x * blockDim.x + threadIdx.x;
    if (idx >= ROWS * CONVD) return;
    int c = idx % CONVD;
    int bl = idx / CONVD;
    int l = bl & 2047;
    const float* base = zx + (size_t)bl * DPROJ + DIN + c;
    float4 w = *(const float4*)(cw + c * 4);
    float a = cb[c];
    if (l >= 3) a = fmaf(base[-3 * DPROJ], w.x, a);
    if (l >= 2) a = fmaf(base[-2 * DPROJ], w.y, a);
    if (l >= 1) a = fmaf(base[-1 * DPROJ], w.z, a);
    a = fmaf(base[0], w.w, a);
    xbc[idx] = a * (1.f / (1.f + __expf(-a)));
}

// ---------------- dt = softplus(raw + bias), dA = exp(dt * -exp(A_log)) --------
__global__ void dtdA_kernel(const float* __restrict__ zx, const float* __restrict__ dtb,
                            const float* __restrict__ Alog,
                            float* __restrict__ dt, float* __restrict__ dA)
{
    int idx = blockIdx.x * blockDim.x + threadIdx.x;
    if (idx >= ROWS * NHM) return;
    int hm = idx & 15;
    int bl = idx >> 4;
    float raw = zx[(size_t)bl * DPROJ + (DPROJ - NHM) + hm] + dtb[hm];
    float dtv = (raw > 20.f) ? raw : log1pf(__expf(raw));
    float dAv = __expf(-__expf(Alog[hm]) * dtv);
    dt[idx] = dtv; dA[idx] = dAv;
}

// ---------------- sequential SSM scan, both directions in one launch ------------
__global__ void scan_kernel(
    const float* __restrict__ xbc0, const float* __restrict__ dt0, const float* __restrict__ dA0,
    const float* __restrict__ Dp0, float* __restrict__ y0,
    const float* __restrict__ xbc1, const float* __restrict__ dt1, const float* __restrict__ dA1,
    const float* __restrict__ Dp1, float* __restrict__ y1)
{
    int z = blockIdx.z;
    int b = z & 1, dir = z >> 1;
    const float* xbc = dir ? xbc1 : xbc0;
    const float* dtp = dir ? dt1 : dt0;
    const float* dAp = dir ? dA1 : dA0;
    const float* Dp  = dir ? Dp1 : Dp0;
    float* y         = dir ? y1 : y0;
    int h = blockIdx.y, pc = blockIdx.x;
    int t = threadIdx.x;
    int p_local = t >> 4, nsub = t & 15, n0c = nsub << 2;

    __shared__ float sm[2][160];

    int kind = 3, roff = 0;
    if (t < 16)       { kind = 0; roff = h * 64 + pc * 16 + t; }
    else if (t < 80)  { kind = 0; roff = DIN + (t - 16); }
    else if (t < 144) { kind = 0; roff = DIN + NNc + (t - 80); }
    else if (t == 144) kind = 1;
    else if (t == 145) kind = 2;

    size_t base_bl = (size_t)b * LL;
    float s0 = 0.f, s1 = 0.f, s2 = 0.f, s3 = 0.f;
    float dcoef = Dp[h];

    float rv = 0.f;
    if (kind == 0)      rv = xbc[base_bl * CONVD + roff];
    else if (kind == 1) rv = dtp[base_bl * NHM + h];
    else if (kind == 2) rv = dAp[base_bl * NHM + h];

    int buf = 0;
    for (int l = 0; l < LL; l++) {
        if (t < 146) sm[buf][t] = rv;
        __syncthreads();
        if (l + 1 < LL) {
            if (kind == 0)      rv = xbc[(base_bl + l + 1) * CONVD + roff];
            else if (kind == 1) rv = dtp[(base_bl + l + 1) * NHM + h];
            else if (kind == 2) rv = dAp[(base_bl + l + 1) * NHM + h];
        }
        float dtv = sm[buf][144];
        float dAv = sm[buf][145];
        float xv  = sm[buf][p_local];
        float cx  = dtv * xv;
        float4 Bv = *(const float4*)&sm[buf][16 + n0c];
        float4 Cv = *(const float4*)&sm[buf][80 + n0c];
        s0 = fmaf(s0, dAv, cx * Bv.x);
        s1 = fmaf(s1, dAv, cx * Bv.y);
        s2 = fmaf(s2, dAv, cx * Bv.z);
        s3 = fmaf(s3, dAv, cx * Bv.w);
        float part = s0 * Cv.x + s1 * Cv.y + s2 * Cv.z + s3 * Cv.w;
        part += __shfl_xor_sync(0xffffffffu, part, 1);
        part += __shfl_xor_sync(0xffffffffu, part, 2);
        part += __shfl_xor_sync(0xffffffffu, part, 4);
        part += __shfl_xor_sync(0xffffffffu, part, 8);
        if (nsub == 0)
            y[(base_bl + l) * DIN + h * 64 + pc * 16 + p_local] = part + dcoef * xv;
        buf ^= 1;
    }
}

// ---------------- gated RMSNorm (in-place on y), warp per 1024-row --------------
__global__ void rmsgate_kernel(float* __restrict__ y, const float* __restrict__ zx,
                               const float* __restrict__ nw)
{
    int warp = (blockIdx.x * blockDim.x + threadIdx.x) >> 5;
    int lane = threadIdx.x & 31;
    if (warp >= ROWS) return;
    const float* zr = zx + (size_t)warp * DPROJ;
    float* yr = y + (size_t)warp * DIN;
    float v[32];
    float ss = 0.f;
#pragma unroll
    for (int i = 0; i < 32; i++) {
        int c = lane + i * 32;
        float zv = zr[c];
        float yv = yr[c] * (zv * (1.f / (1.f + __expf(-zv))));
        v[i] = yv; ss = fmaf(yv, yv, ss);
    }
#pragma unroll
    for (int o = 16; o > 0; o >>= 1) ss += __shfl_xor_sync(0xffffffffu, ss, o);
    float r = rsqrtf(ss * (1.f / DIN) + EPSF);
#pragma unroll
    for (int i = 0; i < 32; i++) {
        int c = lane + i * 32;
        yr[c] = v[i] * r * nw[c];
    }
}

// ---------------- launcher -----------------------------------------------------
extern "C" void kernel_launch(void* const* d_in, const int* in_sizes, int n_in,
                              void* d_out, int out_size)
{
    const float* h      = (const float*)d_in[0];
    const float* Wqkv   = (const float*)d_in[1];
    const float* bqkv   = (const float*)d_in[2];
    const float* Wo_a   = (const float*)d_in[3];
    const float* bo_a   = (const float*)d_in[4];
    const float* g1     = (const float*)d_in[5];
    const float* b1     = (const float*)d_in[6];
    const float* g2     = (const float*)d_in[7];
    const float* b2     = (const float*)d_in[8];
    const float* f_Wi   = (const float*)d_in[9];
    const float* f_cw   = (const float*)d_in[10];
    const float* f_cb   = (const float*)d_in[11];
    const float* f_dtb  = (const float*)d_in[12];
    const float* f_Alog = (const float*)d_in[13];
    const float* f_D    = (const float*)d_in[14];
    const float* f_nw   = (const float*)d_in[15];
    const float* f_Wo   = (const float*)d_in[16];
    const float* bw_Wi  = (const float*)d_in[17];
    const float* bw_cw  = (const float*)d_in[18];
    const float* bw_cb  = (const float*)d_in[19];
    const float* bw_dtb = (const float*)d_in[20];
    const float* bw_Alog= (const float*)d_in[21];
    const float* bw_D   = (const float*)d_in[22];
    const float* bw_nw  = (const float*)d_in[23];
    const float* bw_Wo  = (const float*)d_in[24];
    float* out = (float*)d_out;

    float *qkvb, *attno, *aproj, *h1, *zx0, *zx1, *xbc0, *xbc1;
    float *dt0, *dt1, *dA0, *dA1, *y0, *y1, *acc;
    cudaGetSymbolAddress((void**)&qkvb, g_qkv);
    cudaGetSymbolAddress((void**)&attno, g_attno);
    cudaGetSymbolAddress((void**)&aproj, g_aproj);
    cudaGetSymbolAddress((void**)&h1, g_h1);
    cudaGetSymbolAddress((void**)&zx0, g_zx0);
    cudaGetSymbolAddress((void**)&zx1, g_zx1);
    cudaGetSymbolAddress((void**)&xbc0, g_xbc0);
    cudaGetSymbolAddress((void**)&xbc1, g_xbc1);
    cudaGetSymbolAddress((void**)&dt0, g_dt0);
    cudaGetSymbolAddress((void**)&dt1, g_dt1);
    cudaGetSymbolAddress((void**)&dA0, g_dA0);
    cudaGetSymbolAddress((void**)&dA1, g_dA1);
    cudaGetSymbolAddress((void**)&y0, g_y0);
    cudaGetSymbolAddress((void**)&y1, g_y1);
    cudaGetSymbolAddress((void**)&acc, g_acc);

    // 1) qkv = h @ Wqkv^T + bqkv
    gemm_nt<<<dim3(24, 32), 256>>>(h, Wqkv, bqkv, nullptr, qkvb, 1536, 512, 0, 0, 0);
    // 2) attention
    attn_kernel<<<dim3(32, 32, 2), 64>>>(qkvb, attno);
    // 3) attn out-proj
    gemm_nt<<<dim3(8, 32), 256>>>(attno, Wo_a, bo_a, nullptr, aproj, 512, 512, 0, 0, 0);
    // 4) h1 = LN(h + aproj)
    ln_kernel<<<512, 256>>>(h, aproj, g1, b1, h1);
    // 5) mamba in-projections (fwd; bwd reads h1 reversed)
    gemm_nt<<<dim3(35, 32), 256>>>(h1, f_Wi, nullptr, nullptr, zx0, DPROJ, 512, 0, 0, 0);
    gemm_nt<<<dim3(35, 32), 256>>>(h1, bw_Wi, nullptr, nullptr, zx1, DPROJ, 512, 1, 0, 0);
    // 6) depthwise conv + silu
    conv_kernel<<<(ROWS * CONVD + 255) / 256, 256>>>(zx0, f_cw, f_cb, xbc0);
    conv_kernel<<<(ROWS * CONVD + 255) / 256, 256>>>(zx1, bw_cw, bw_cb, xbc1);
    // 7) dt / dA
    dtdA_kernel<<<256, 256>>>(zx0, f_dtb, f_Alog, dt0, dA0);
    dtdA_kernel<<<256, 256>>>(zx1, bw_dtb, bw_Alog, dt1, dA1);
    // 8) SSM scan, both directions concurrently
    scan_kernel<<<dim3(4, 16, 4), 256>>>(xbc0, dt0, dA0, f_D, y0,
                                         xbc1, dt1, dA1, bw_D, y1);
    // 9) gated RMSNorm (in place)
    rmsgate_kernel<<<512, 256>>>(y0, zx0, f_nw);
    rmsgate_kernel<<<512, 256>>>(y1, zx1, bw_nw);
    // 10) out-projections: acc = h1 + yf@Wo^T ; acc[rev] += yb@Wo^T
    gemm_nt<<<dim3(8, 32), 256>>>(y0, f_Wo, nullptr, h1, acc, 512, 1024, 0, 0, 0);
    gemm_nt<<<dim3(8, 32), 256>>>(y1, bw_Wo, nullptr, nullptr, acc, 512, 1024, 0, 1, 1);
    // 11) final LN
    ln_kernel<<<512, 256>>>(acc, nullptr, g2, b2, out);
}